// round 2
// baseline (speedup 1.0000x reference)
#include <cuda_runtime.h>
#include <cstdint>

#define BTOK 4096
#define DDIM 2048
#define HDIM 2048
#define NEXP 8

// ---------------- static device scratch (allocations are forbidden) ----------
__device__ int   g_cnt[NEXP];
__device__ int   g_tok[NEXP][BTOK];
__device__ float g_w[NEXP][BTOK];

// ---------------- zero output + counters ------------------------------------
__global__ void k_zero(float4* __restrict__ out4) {
    long i = (long)blockIdx.x * blockDim.x + threadIdx.x;
    out4[i] = make_float4(0.f, 0.f, 0.f, 0.f);
    if (blockIdx.x == 0 && threadIdx.x < NEXP) g_cnt[threadIdx.x] = 0;
}

// ---------------- gating: softmax + top-2 routing ----------------------------
// one warp per token; blockDim = (32, 8)
__global__ void k_gate(const float* __restrict__ x,
                       const float* __restrict__ Wg,
                       const float* __restrict__ bg) {
    int b    = blockIdx.x * 8 + threadIdx.y;
    int lane = threadIdx.x;

    const float* xr = x + (size_t)b * DDIM;
    float acc[NEXP];
#pragma unroll
    for (int e = 0; e < NEXP; e++) acc[e] = 0.f;

    for (int c = lane; c < DDIM; c += 32) {
        float xv = xr[c];
        const float4* w4 = reinterpret_cast<const float4*>(Wg + (size_t)c * NEXP);
        float4 w0 = w4[0], w1 = w4[1];
        acc[0] += xv * w0.x;  acc[1] += xv * w0.y;
        acc[2] += xv * w0.z;  acc[3] += xv * w0.w;
        acc[4] += xv * w1.x;  acc[5] += xv * w1.y;
        acc[6] += xv * w1.z;  acc[7] += xv * w1.w;
    }
#pragma unroll
    for (int off = 16; off > 0; off >>= 1) {
#pragma unroll
        for (int e = 0; e < NEXP; e++)
            acc[e] += __shfl_xor_sync(0xFFFFFFFFu, acc[e], off);
    }

    if (lane == 0) {
        float lg[NEXP];
        float mx = -1e30f;
#pragma unroll
        for (int e = 0; e < NEXP; e++) { lg[e] = acc[e] + bg[e]; mx = fmaxf(mx, lg[e]); }
        float s = 0.f;
        float p[NEXP];
#pragma unroll
        for (int e = 0; e < NEXP; e++) { p[e] = expf(lg[e] - mx); s += p[e]; }
        float inv = 1.f / s;

        // top-2, jax.lax.top_k tie semantics (lowest index wins on ties)
        int i1 = 0;
#pragma unroll
        for (int e = 1; e < NEXP; e++) if (lg[e] > lg[i1]) i1 = e;
        int i2 = -1;
#pragma unroll
        for (int e = 0; e < NEXP; e++)
            if (e != i1 && (i2 < 0 || lg[e] > lg[i2])) i2 = e;

        int p1 = atomicAdd(&g_cnt[i1], 1);
        g_tok[i1][p1] = b;  g_w[i1][p1] = p[i1] * inv;
        int p2 = atomicAdd(&g_cnt[i2], 1);
        g_tok[i2][p2] = b;  g_w[i2][p2] = p[i2] * inv;
    }
}

// ---------------- gathered per-expert SGEMM ----------------------------------
// grid = (BTOK/128, HDIM/128, NEXP), 256 threads, 8x8 micro-tile
#define BM 128
#define BN 128
#define BK 16

__global__ void __launch_bounds__(256) k_gemm(const float* __restrict__ x,
                                              const float* __restrict__ We,
                                              const float* __restrict__ be,
                                              float* __restrict__ out) {
    const int e   = blockIdx.z;
    const int cnt = g_cnt[e];
    const int m0  = blockIdx.x * BM;
    if (m0 >= cnt) return;
    const int n0  = blockIdx.y * BN;

    __shared__ float As[BK][BM];
    __shared__ float Bs[BK][BN];

    const int tid = threadIdx.x;
    const int ty  = tid / 16;        // 0..15
    const int tx  = tid % 16;        // 0..15

    // A-load mapping: each thread loads 8 consecutive k for one gathered row
    const int am  = tid >> 1;               // 0..127 (row within tile)
    const int akb = (tid & 1) * 8;          // k sub-block 0 or 8
    const int mm  = min(m0 + am, cnt - 1);
    const int tokRow = g_tok[e][mm];
    const float* aSrcBase = x + (size_t)tokRow * DDIM + akb;

    // B-load mapping: thread -> (kk = tid/16, n = (tid%16)*8)
    const int bkk = tid / 16;
    const int bn  = (tid % 16) * 8;
    const float* bSrcBase = We + (size_t)e * DDIM * HDIM + (size_t)bkk * HDIM + n0 + bn;

    float accv[8][8];
#pragma unroll
    for (int i = 0; i < 8; i++)
#pragma unroll
        for (int j = 0; j < 8; j++) accv[i][j] = 0.f;

    for (int k0 = 0; k0 < DDIM; k0 += BK) {
        // load A tile (gathered rows)
        {
            const float4* s = reinterpret_cast<const float4*>(aSrcBase + k0);
            float4 v0 = s[0], v1 = s[1];
            As[akb + 0][am] = v0.x;  As[akb + 1][am] = v0.y;
            As[akb + 2][am] = v0.z;  As[akb + 3][am] = v0.w;
            As[akb + 4][am] = v1.x;  As[akb + 5][am] = v1.y;
            As[akb + 6][am] = v1.z;  As[akb + 7][am] = v1.w;
        }
        // load B tile
        {
            const float4* s = reinterpret_cast<const float4*>(bSrcBase + (size_t)k0 * HDIM);
            float4 v0 = s[0], v1 = s[1];
            *reinterpret_cast<float4*>(&Bs[bkk][bn])     = v0;
            *reinterpret_cast<float4*>(&Bs[bkk][bn + 4]) = v1;
        }
        __syncthreads();

#pragma unroll
        for (int kk = 0; kk < BK; kk++) {
            float4 a0 = *reinterpret_cast<const float4*>(&As[kk][ty * 8]);
            float4 a1 = *reinterpret_cast<const float4*>(&As[kk][ty * 8 + 4]);
            float4 b0 = *reinterpret_cast<const float4*>(&Bs[kk][tx * 8]);
            float4 b1 = *reinterpret_cast<const float4*>(&Bs[kk][tx * 8 + 4]);
            float a[8] = {a0.x, a0.y, a0.z, a0.w, a1.x, a1.y, a1.z, a1.w};
            float bb[8] = {b0.x, b0.y, b0.z, b0.w, b1.x, b1.y, b1.z, b1.w};
#pragma unroll
            for (int i = 0; i < 8; i++)
#pragma unroll
                for (int j = 0; j < 8; j++)
                    accv[i][j] = fmaf(a[i], bb[j], accv[i][j]);
        }
        __syncthreads();
    }

    // epilogue: out[b, n] += w * (acc + be[e, n]); exactly 2 adds/element -> deterministic
#pragma unroll
    for (int i = 0; i < 8; i++) {
        int m = m0 + ty * 8 + i;
        if (m < cnt) {
            int   brow = g_tok[e][m];
            float w    = g_w[e][m];
            float* orow = out + (size_t)brow * HDIM + n0 + tx * 8;
            const float* berow = be + (size_t)e * HDIM + n0 + tx * 8;
#pragma unroll
            for (int j = 0; j < 8; j++)
                atomicAdd(&orow[j], w * (accv[i][j] + berow[j]));
        }
    }
}

// ---------------- launch ------------------------------------------------------
extern "C" void kernel_launch(void* const* d_in, const int* in_sizes, int n_in,
                              void* d_out, int out_size) {
    const float* x  = (const float*)d_in[0];
    const float* Wg = (const float*)d_in[1];
    const float* bg = (const float*)d_in[2];
    const float* We = (const float*)d_in[3];
    const float* be = (const float*)d_in[4];
    float* out = (float*)d_out;

    // zero output (8388608 floats = 2097152 float4) + counters
    k_zero<<<8192, 256>>>((float4*)out);

    // gating: 4096 tokens, 8 warps/block
    k_gate<<<BTOK / 8, dim3(32, 8)>>>(x, Wg, bg);

    // gathered per-expert GEMM
    dim3 grid(BTOK / BM, HDIM / BN, NEXP);
    k_gemm<<<grid, 256>>>(x, We, be, out);
}

// round 5
// speedup vs baseline: 2.7494x; 2.7494x over previous
#include <cuda_runtime.h>
#include <cstdint>

#define BTOK 4096
#define DDIM 2048
#define HDIM 2048
#define NEXP 8

// ---------------- static device scratch (allocations are forbidden) ----------
__device__ int   g_cnt[NEXP];
__device__ int   g_tok[NEXP][BTOK];
__device__ float g_w[NEXP][BTOK];

// ---------------- helpers ----------------------------------------------------
__device__ __forceinline__ uint32_t smem_u32(const void* p) {
    uint32_t a;
    asm("{ .reg .u64 t; cvta.to.shared.u64 t, %1; cvt.u32.u64 %0, t; }" : "=r"(a) : "l"(p));
    return a;
}
__device__ __forceinline__ uint32_t f2tf32(float f) {
    uint32_t r; asm("cvt.rna.tf32.f32 %0, %1;" : "=r"(r) : "f"(f)); return r;
}
#define CPA16(dst, src) \
    asm volatile("cp.async.cg.shared.global [%0], [%1], 16;" :: "r"(dst), "l"(src) : "memory")
#define CPA_COMMIT() asm volatile("cp.async.commit_group;" ::: "memory")
#define CPA_WAIT1()  asm volatile("cp.async.wait_group 1;" ::: "memory")

__device__ __forceinline__ void mma_tf32(float* c, const uint32_t* a, const uint32_t* b) {
    asm volatile(
        "mma.sync.aligned.m16n8k8.row.col.f32.tf32.tf32.f32 "
        "{%0,%1,%2,%3}, {%4,%5,%6,%7}, {%8,%9}, {%0,%1,%2,%3};"
        : "+f"(c[0]), "+f"(c[1]), "+f"(c[2]), "+f"(c[3])
        : "r"(a[0]), "r"(a[1]), "r"(a[2]), "r"(a[3]), "r"(b[0]), "r"(b[1]));
}

// ---------------- zero output + counters -------------------------------------
__global__ void k_zero(float4* __restrict__ out4) {
    long i = (long)blockIdx.x * blockDim.x + threadIdx.x;
    out4[i] = make_float4(0.f, 0.f, 0.f, 0.f);
    if (blockIdx.x == 0 && threadIdx.x < NEXP) g_cnt[threadIdx.x] = 0;
}

// ---------------- gating: softmax + top-2 routing ----------------------------
__global__ void k_gate(const float* __restrict__ x,
                       const float* __restrict__ Wg,
                       const float* __restrict__ bg) {
    int b    = blockIdx.x * 8 + threadIdx.y;
    int lane = threadIdx.x;
    const float* xr = x + (size_t)b * DDIM;
    float acc[NEXP];
#pragma unroll
    for (int e = 0; e < NEXP; e++) acc[e] = 0.f;
    for (int c = lane; c < DDIM; c += 32) {
        float xv = xr[c];
        const float4* w4 = reinterpret_cast<const float4*>(Wg + (size_t)c * NEXP);
        float4 w0 = w4[0], w1 = w4[1];
        acc[0] += xv * w0.x;  acc[1] += xv * w0.y;
        acc[2] += xv * w0.z;  acc[3] += xv * w0.w;
        acc[4] += xv * w1.x;  acc[5] += xv * w1.y;
        acc[6] += xv * w1.z;  acc[7] += xv * w1.w;
    }
#pragma unroll
    for (int off = 16; off > 0; off >>= 1)
#pragma unroll
        for (int e = 0; e < NEXP; e++)
            acc[e] += __shfl_xor_sync(0xFFFFFFFFu, acc[e], off);

    if (lane == 0) {
        float lg[NEXP], p[NEXP];
        float mx = -1e30f;
#pragma unroll
        for (int e = 0; e < NEXP; e++) { lg[e] = acc[e] + bg[e]; mx = fmaxf(mx, lg[e]); }
        float s = 0.f;
#pragma unroll
        for (int e = 0; e < NEXP; e++) { p[e] = expf(lg[e] - mx); s += p[e]; }
        float inv = 1.f / s;
        int i1 = 0;
#pragma unroll
        for (int e = 1; e < NEXP; e++) if (lg[e] > lg[i1]) i1 = e;
        int i2 = -1;
#pragma unroll
        for (int e = 0; e < NEXP; e++)
            if (e != i1 && (i2 < 0 || lg[e] > lg[i2])) i2 = e;
        int p1 = atomicAdd(&g_cnt[i1], 1);
        g_tok[i1][p1] = b;  g_w[i1][p1] = p[i1] * inv;
        int p2 = atomicAdd(&g_cnt[i2], 1);
        g_tok[i2][p2] = b;  g_w[i2][p2] = p[i2] * inv;
    }
}

// ---------------- gathered mma.sync tf32 GEMM --------------------------------
// grid (BTOK/128, HDIM/128, NEXP), 256 threads (8 warps, 2x4 warp grid, 64x32/warp)
#define BK 32
#define A_STR 36          // floats per A smem row (128 rows) -> banks 4m+k conflict-free
#define B_STR 136         // floats per B smem row (32 rows)  -> banks 8k+n conflict-free
#define A_BYTES (128 * A_STR * 4)          // 18432
#define B_BYTES (BK * B_STR * 4)           // 17408
#define STAGE_BYTES (A_BYTES + B_BYTES)    // 35840
#define SMEM_TOTAL (2 * STAGE_BYTES)       // 71680
#define NKC (DDIM / BK)                    // 64

__global__ void __launch_bounds__(256, 2) k_gemm(const float* __restrict__ x,
                                                 const float* __restrict__ We,
                                                 const float* __restrict__ be,
                                                 float* __restrict__ out) {
    const int e   = blockIdx.z;
    const int cnt = g_cnt[e];
    const int m0  = blockIdx.x * 128;
    if (m0 >= cnt) return;
    const int n0  = blockIdx.y * 128;

    extern __shared__ char smem[];
    const uint32_t sb = smem_u32(smem);
    const int tid  = threadIdx.x;
    const int wid  = tid / 32, lane = tid % 32;
    const int g    = lane >> 2, t4 = lane & 3;
    const int wm   = (wid & 1) * 64;     // warp M origin
    const int wn   = (wid >> 1) * 32;    // warp N origin

    // ---- global source pointers ----
    // A: thread -> (row = tid/2, half = tid&1 covering 16 floats)
    const int aRow  = tid >> 1;
    const int aColF = (tid & 1) * 16;
    const int mIdx  = min(m0 + aRow, cnt - 1);
    const float* aSrc = x + (size_t)g_tok[e][mIdx] * DDIM + aColF;
    const uint32_t aDst = sb + (uint32_t)(aRow * A_STR + aColF) * 4;
    // B: 4 passes; pass p: row = p*8 + tid/32, colf = (tid%32)*4
    const int bRow0 = tid >> 5;
    const int bColF = (tid & 31) * 4;
    const float* bSrc = We + (size_t)e * DDIM * HDIM + (size_t)bRow0 * HDIM + n0 + bColF;
    const uint32_t bDst = sb + (uint32_t)A_BYTES + (uint32_t)(bRow0 * B_STR + bColF) * 4;

    // ---- accumulators ----
    float acc[4][4][4];
#pragma unroll
    for (int i = 0; i < 4; i++)
#pragma unroll
        for (int j = 0; j < 4; j++)
#pragma unroll
            for (int c = 0; c < 4; c++) acc[i][j][c] = 0.f;

    // ---- tile loader ----
    auto load_tiles = [&](int kc, int st) {
        const uint32_t so = (uint32_t)(st * STAGE_BYTES);
        const float* ap = aSrc + kc * BK;
#pragma unroll
        for (int c = 0; c < 4; c++)
            CPA16(aDst + so + c * 16, ap + c * 4);
        const float* bp = bSrc + (size_t)(kc * BK) * HDIM;
#pragma unroll
        for (int p = 0; p < 4; p++)
            CPA16(bDst + so + (uint32_t)(p * 8 * B_STR) * 4,
                  bp + (size_t)(p * 8) * HDIM);
    };

    // ---- prologue ----
    load_tiles(0, 0); CPA_COMMIT();
    load_tiles(1, 1); CPA_COMMIT();

    // ---- main loop ----
    for (int kc = 0; kc < NKC; kc++) {
        const int st = kc & 1;
        CPA_WAIT1();
        __syncthreads();

        const float* As = reinterpret_cast<const float*>(smem + st * STAGE_BYTES);
        const float* Bs = reinterpret_cast<const float*>(smem + st * STAGE_BYTES + A_BYTES);

#pragma unroll
        for (int kk = 0; kk < 4; kk++) {
            const int k0 = kk * 8 + t4;
            uint32_t a[4][4], b[4][2];
#pragma unroll
            for (int i = 0; i < 4; i++) {
                const float* ap = As + (wm + i * 16 + g) * A_STR + k0;
                a[i][0] = f2tf32(ap[0]);
                a[i][2] = f2tf32(ap[4]);
                a[i][1] = f2tf32(ap[8 * A_STR]);
                a[i][3] = f2tf32(ap[8 * A_STR + 4]);
            }
#pragma unroll
            for (int j = 0; j < 4; j++) {
                const float* bp = Bs + k0 * B_STR + wn + j * 8 + g;
                b[j][0] = f2tf32(bp[0]);
                b[j][1] = f2tf32(bp[4 * B_STR]);
            }
#pragma unroll
            for (int i = 0; i < 4; i++)
#pragma unroll
                for (int j = 0; j < 4; j++)
                    mma_tf32(acc[i][j], a[i], b[j]);
        }
        __syncthreads();

        if (kc + 2 < NKC) load_tiles(kc + 2, st);
        CPA_COMMIT();            // always commit: keeps wait_group accounting uniform
    }

    // ---- epilogue: out[b,n] += w * (acc + be[e,n])  (2 fp32 adds/elem) ----
    const float* beRow = be + (size_t)e * HDIM + n0;
#pragma unroll
    for (int i = 0; i < 4; i++) {
#pragma unroll
        for (int half = 0; half < 2; half++) {
            const int ml = wm + i * 16 + g + half * 8;
            const int m  = m0 + ml;
            if (m < cnt) {
                const int   token = g_tok[e][m];
                const float wgt   = g_w[e][m];
                float* orow = out + (size_t)token * HDIM + n0;
#pragma unroll
                for (int j = 0; j < 4; j++) {
                    const int n = wn + j * 8 + t4 * 2;
                    const float c0 = acc[i][j][half * 2 + 0];
                    const float c1 = acc[i][j][half * 2 + 1];
                    atomicAdd(&orow[n],     wgt * (c0 + beRow[n]));
                    atomicAdd(&orow[n + 1], wgt * (c1 + beRow[n + 1]));
                }
            }
        }
    }
}

// ---------------- launch ------------------------------------------------------
extern "C" void kernel_launch(void* const* d_in, const int* in_sizes, int n_in,
                              void* d_out, int out_size) {
    const float* x  = (const float*)d_in[0];
    const float* Wg = (const float*)d_in[1];
    const float* bg = (const float*)d_in[2];
    const float* We = (const float*)d_in[3];
    const float* be = (const float*)d_in[4];
    float* out = (float*)d_out;

    cudaFuncSetAttribute(k_gemm, cudaFuncAttributeMaxDynamicSharedMemorySize, SMEM_TOTAL);

    k_zero<<<8192, 256>>>((float4*)out);
    k_gate<<<BTOK / 8, dim3(32, 8)>>>(x, Wg, bg);
    dim3 grid(BTOK / 128, HDIM / 128, NEXP);
    k_gemm<<<grid, 256, SMEM_TOTAL>>>(x, We, be, out);
}